// round 1
// baseline (speedup 1.0000x reference)
#include <cuda_runtime.h>
#include <cstdint>

// Problem constants (fixed by dataset metadata)
#define TTOK 2048
#define HSD  2048
#define IMZD 1408
#define NEXP 32

#define BN  128   // N tile per block
#define KT  16    // K tile per stage
#define SA  20    // A smem row stride (floats) -> conflict-reduced frag reads
#define SB  136   // B smem row stride (floats) -> k-rows land 8 banks apart

// Scratch for intermediate activations (silu(gate)*up), fp32.
__device__ float g_inter[(size_t)TTOK * IMZD];

__device__ __forceinline__ unsigned f2tf(float x) {
    unsigned u;
    asm("cvt.rna.tf32.f32 %0, %1;" : "=r"(u) : "f"(x));
    return u;
}

__device__ __forceinline__ void mma8(float* c, const unsigned* a, const unsigned* b) {
    asm volatile(
        "mma.sync.aligned.m16n8k8.row.col.f32.tf32.tf32.f32 "
        "{%0,%1,%2,%3}, {%4,%5,%6,%7}, {%8,%9}, {%0,%1,%2,%3};"
        : "+f"(c[0]), "+f"(c[1]), "+f"(c[2]), "+f"(c[3])
        : "r"(a[0]), "r"(a[1]), "r"(a[2]), "r"(a[3]),
          "r"(b[0]), "r"(b[1]));
}

// ---------------------------------------------------------------------------
// Kernel 1: per expert e, per N-tile: gate = X@Wg, up = X@Wu, inter = silu(gate)*up
// Block: 256 threads (8 warps, 2x4 warp grid of 32x32 warp tiles), tile 64x128.
// ---------------------------------------------------------------------------
__global__ __launch_bounds__(256, 1) void moe_gateup(
    const float* __restrict__ X,
    const float* __restrict__ Wg,
    const float* __restrict__ Wu,
    const int*   __restrict__ gsz)
{
    const int e  = blockIdx.y;
    const int n0 = blockIdx.x * BN;

    int row_start = 0;
    for (int i = 0; i < e; i++) row_start += gsz[i];
    const int gs = gsz[e];   // rows for this expert (64 for this dataset)

    __shared__ unsigned As[2][64 * SA];
    __shared__ unsigned Bg[2][KT * SB];
    __shared__ unsigned Bu[2][KT * SB];

    const int tid  = threadIdx.x;
    const int lane = tid & 31;
    const int warp = tid >> 5;
    const int wm   = warp & 1;   // 0..1  -> 32-row half
    const int wn   = warp >> 1;  // 0..3  -> 32-col quarter

    const float* wg = Wg + (size_t)e * HSD * IMZD + n0;
    const float* wu = Wu + (size_t)e * HSD * IMZD + n0;

    // A load map: thread -> m = tid/4, k offset = (tid%4)*4  (64x16 tile, float4)
    const int am = tid >> 2;
    const int ak = (tid & 3) * 4;

    float accG[2][4][4], accU[2][4][4];
    #pragma unroll
    for (int i = 0; i < 2; i++)
        #pragma unroll
        for (int j = 0; j < 4; j++)
            #pragma unroll
            for (int k = 0; k < 4; k++) { accG[i][j][k] = 0.f; accU[i][j][k] = 0.f; }

    float4 aR;
    float4 bgR[2], buR[2];

    const int NK = HSD / KT;  // 128 stages

    auto load_stage = [&](int kt) {
        const int k = kt * KT;
        if (am < gs) aR = *(const float4*)(X + (size_t)(row_start + am) * HSD + k + ak);
        else         aR = make_float4(0.f, 0.f, 0.f, 0.f);
        #pragma unroll
        for (int i = 0; i < 2; i++) {
            int f   = tid + i * 256;      // 512 float4s cover 16x128
            int row = f >> 5;
            int c4  = (f & 31) * 4;
            bgR[i] = *(const float4*)(wg + (size_t)(k + row) * IMZD + c4);
            buR[i] = *(const float4*)(wu + (size_t)(k + row) * IMZD + c4);
        }
    };

    auto store_stage = [&](int b) {
        uint4 va;
        va.x = f2tf(aR.x); va.y = f2tf(aR.y); va.z = f2tf(aR.z); va.w = f2tf(aR.w);
        *(uint4*)&As[b][am * SA + ak] = va;
        #pragma unroll
        for (int i = 0; i < 2; i++) {
            int f   = tid + i * 256;
            int row = f >> 5;
            int c4  = (f & 31) * 4;
            uint4 vg, vu;
            vg.x = f2tf(bgR[i].x); vg.y = f2tf(bgR[i].y);
            vg.z = f2tf(bgR[i].z); vg.w = f2tf(bgR[i].w);
            vu.x = f2tf(buR[i].x); vu.y = f2tf(buR[i].y);
            vu.z = f2tf(buR[i].z); vu.w = f2tf(buR[i].w);
            *(uint4*)&Bg[b][row * SB + c4] = vg;
            *(uint4*)&Bu[b][row * SB + c4] = vu;
        }
    };

    auto compute = [&](int b) {
        const unsigned* as = As[b];
        const unsigned* bg = Bg[b];
        const unsigned* bu = Bu[b];
        #pragma unroll
        for (int k8 = 0; k8 < 2; k8++) {
            const int kb = k8 * 8;
            unsigned a[2][4];
            #pragma unroll
            for (int mt = 0; mt < 2; mt++) {
                int r = wm * 32 + mt * 16 + (lane >> 2);
                int c = kb + (lane & 3);
                a[mt][0] = as[r * SA + c];
                a[mt][1] = as[(r + 8) * SA + c];
                a[mt][2] = as[r * SA + c + 4];
                a[mt][3] = as[(r + 8) * SA + c + 4];
            }
            #pragma unroll
            for (int nt = 0; nt < 4; nt++) {
                int col = wn * 32 + nt * 8 + (lane >> 2);
                int kr  = kb + (lane & 3);
                unsigned bGf[2] = { bg[kr * SB + col], bg[(kr + 4) * SB + col] };
                unsigned bUf[2] = { bu[kr * SB + col], bu[(kr + 4) * SB + col] };
                #pragma unroll
                for (int mt = 0; mt < 2; mt++) {
                    mma8(accG[mt][nt], a[mt], bGf);
                    mma8(accU[mt][nt], a[mt], bUf);
                }
            }
        }
    };

    load_stage(0);
    store_stage(0);
    __syncthreads();

    for (int kt = 0; kt < NK; kt++) {
        const int cur = kt & 1;
        if (kt + 1 < NK) load_stage(kt + 1);
        compute(cur);
        __syncthreads();
        if (kt + 1 < NK) store_stage(cur ^ 1);
        __syncthreads();
    }

    // Epilogue: silu(gate)*up -> g_inter
    #pragma unroll
    for (int mt = 0; mt < 2; mt++) {
        int r0 = wm * 32 + mt * 16 + (lane >> 2);
        #pragma unroll
        for (int nt = 0; nt < 4; nt++) {
            int c0 = n0 + wn * 32 + nt * 8 + 2 * (lane & 3);
            const float* cg = accG[mt][nt];
            const float* cu = accU[mt][nt];
            if (r0 < gs) {
                float g0 = cg[0], g1 = cg[1];
                float v0 = (g0 / (1.f + __expf(-g0))) * cu[0];
                float v1 = (g1 / (1.f + __expf(-g1))) * cu[1];
                *(float2*)&g_inter[(size_t)(row_start + r0) * IMZD + c0] = make_float2(v0, v1);
            }
            if (r0 + 8 < gs) {
                float g2 = cg[2], g3 = cg[3];
                float v2 = (g2 / (1.f + __expf(-g2))) * cu[2];
                float v3 = (g3 / (1.f + __expf(-g3))) * cu[3];
                *(float2*)&g_inter[(size_t)(row_start + r0 + 8) * IMZD + c0] = make_float2(v2, v3);
            }
        }
    }
}

// ---------------------------------------------------------------------------
// Kernel 2: out = inter @ Wd[e]   ([64,1408] x [1408,2048] per expert)
// ---------------------------------------------------------------------------
__global__ __launch_bounds__(256, 1) void moe_down(
    const float* __restrict__ Wd,
    const int*   __restrict__ gsz,
    float*       __restrict__ out)
{
    const int e  = blockIdx.y;
    const int n0 = blockIdx.x * BN;

    int row_start = 0;
    for (int i = 0; i < e; i++) row_start += gsz[i];
    const int gs = gsz[e];

    __shared__ unsigned As[2][64 * SA];
    __shared__ unsigned Bs[2][KT * SB];

    const int tid  = threadIdx.x;
    const int lane = tid & 31;
    const int warp = tid >> 5;
    const int wm   = warp & 1;
    const int wn   = warp >> 1;

    const float* wd = Wd + (size_t)e * IMZD * HSD + n0;

    const int am = tid >> 2;
    const int ak = (tid & 3) * 4;

    float acc[2][4][4];
    #pragma unroll
    for (int i = 0; i < 2; i++)
        #pragma unroll
        for (int j = 0; j < 4; j++)
            #pragma unroll
            for (int k = 0; k < 4; k++) acc[i][j][k] = 0.f;

    float4 aR;
    float4 bR[2];

    const int NK = IMZD / KT;  // 88 stages

    auto load_stage = [&](int kt) {
        const int k = kt * KT;
        if (am < gs) aR = *(const float4*)(g_inter + (size_t)(row_start + am) * IMZD + k + ak);
        else         aR = make_float4(0.f, 0.f, 0.f, 0.f);
        #pragma unroll
        for (int i = 0; i < 2; i++) {
            int f   = tid + i * 256;
            int row = f >> 5;
            int c4  = (f & 31) * 4;
            bR[i] = *(const float4*)(wd + (size_t)(k + row) * HSD + c4);
        }
    };

    auto store_stage = [&](int b) {
        uint4 va;
        va.x = f2tf(aR.x); va.y = f2tf(aR.y); va.z = f2tf(aR.z); va.w = f2tf(aR.w);
        *(uint4*)&As[b][am * SA + ak] = va;
        #pragma unroll
        for (int i = 0; i < 2; i++) {
            int f   = tid + i * 256;
            int row = f >> 5;
            int c4  = (f & 31) * 4;
            uint4 vb;
            vb.x = f2tf(bR[i].x); vb.y = f2tf(bR[i].y);
            vb.z = f2tf(bR[i].z); vb.w = f2tf(bR[i].w);
            *(uint4*)&Bs[b][row * SB + c4] = vb;
        }
    };

    auto compute = [&](int b) {
        const unsigned* as = As[b];
        const unsigned* bs = Bs[b];
        #pragma unroll
        for (int k8 = 0; k8 < 2; k8++) {
            const int kb = k8 * 8;
            unsigned a[2][4];
            #pragma unroll
            for (int mt = 0; mt < 2; mt++) {
                int r = wm * 32 + mt * 16 + (lane >> 2);
                int c = kb + (lane & 3);
                a[mt][0] = as[r * SA + c];
                a[mt][1] = as[(r + 8) * SA + c];
                a[mt][2] = as[r * SA + c + 4];
                a[mt][3] = as[(r + 8) * SA + c + 4];
            }
            #pragma unroll
            for (int nt = 0; nt < 4; nt++) {
                int col = wn * 32 + nt * 8 + (lane >> 2);
                int kr  = kb + (lane & 3);
                unsigned bf[2] = { bs[kr * SB + col], bs[(kr + 4) * SB + col] };
                #pragma unroll
                for (int mt = 0; mt < 2; mt++) {
                    mma8(acc[mt][nt], a[mt], bf);
                }
            }
        }
    };

    load_stage(0);
    store_stage(0);
    __syncthreads();

    for (int kt = 0; kt < NK; kt++) {
        const int cur = kt & 1;
        if (kt + 1 < NK) load_stage(kt + 1);
        compute(cur);
        __syncthreads();
        if (kt + 1 < NK) store_stage(cur ^ 1);
        __syncthreads();
    }

    // Epilogue: write output tile
    #pragma unroll
    for (int mt = 0; mt < 2; mt++) {
        int r0 = wm * 32 + mt * 16 + (lane >> 2);
        #pragma unroll
        for (int nt = 0; nt < 4; nt++) {
            int c0 = n0 + wn * 32 + nt * 8 + 2 * (lane & 3);
            const float* c = acc[mt][nt];
            if (r0 < gs)
                *(float2*)&out[(size_t)(row_start + r0) * HSD + c0] = make_float2(c[0], c[1]);
            if (r0 + 8 < gs)
                *(float2*)&out[(size_t)(row_start + r0 + 8) * HSD + c0] = make_float2(c[2], c[3]);
        }
    }
}

extern "C" void kernel_launch(void* const* d_in, const int* in_sizes, int n_in,
                              void* d_out, int out_size) {
    const float* X  = (const float*)d_in[0];  // hidden_states [T, HS]
    const float* Wg = (const float*)d_in[1];  // gate_kernel   [E, HS, IMZ]
    const float* Wu = (const float*)d_in[2];  // up_kernel     [E, HS, IMZ]
    const float* Wd = (const float*)d_in[3];  // down_kernel   [E, IMZ, HS]
    const int*   gs = (const int*)d_in[4];    // group_sizes   [E]
    float* out = (float*)d_out;               // [T, HS] fp32

    moe_gateup<<<dim3(IMZD / BN, NEXP), 256>>>(X, Wg, Wu, gs);
    moe_down  <<<dim3(HSD  / BN, NEXP), 256>>>(Wd, gs, out);
}

// round 10
// speedup vs baseline: 1.7246x; 1.7246x over previous
#include <cuda_runtime.h>
#include <cstdint>

// Problem constants (fixed by dataset metadata)
#define TTOK 2048
#define HSD  2048
#define IMZD 1408
#define NEXP 32

#define BN  128   // N tile per block
#define KT  16    // K tile per stage
#define SA  20    // A smem row stride (floats): conflict-free frag reads, 16B-aligned rows
#define SB  136   // B smem row stride (floats): conflict-free frag reads, 16B-aligned rows
#define STAGES 4

#define AW (64 * SA)        // A tile words per stage (1280)
#define BW (KT * SB)        // B tile words per stage (2176)
#define STW_GU (AW + 2*BW)  // gateup stage words (5632)
#define STW_DN (AW + BW)    // down stage words   (3456)

// Scratch for intermediate activations (silu(gate)*up), fp32.
__device__ float g_inter[(size_t)TTOK * IMZD];

__device__ __forceinline__ unsigned f2tf(float x) {
    unsigned u;
    asm("cvt.rna.tf32.f32 %0, %1;" : "=r"(u) : "f"(x));
    return u;
}

__device__ __forceinline__ void mma8(float* c, const unsigned* a, const unsigned* b) {
    asm volatile(
        "mma.sync.aligned.m16n8k8.row.col.f32.tf32.tf32.f32 "
        "{%0,%1,%2,%3}, {%4,%5,%6,%7}, {%8,%9}, {%0,%1,%2,%3};"
        : "+f"(c[0]), "+f"(c[1]), "+f"(c[2]), "+f"(c[3])
        : "r"(a[0]), "r"(a[1]), "r"(a[2]), "r"(a[3]),
          "r"(b[0]), "r"(b[1]));
}

__device__ __forceinline__ uint32_t sptr(const void* p) {
    return (uint32_t)__cvta_generic_to_shared(p);
}
__device__ __forceinline__ void cpa16(uint32_t dst, const float* src, int srcsz) {
    asm volatile("cp.async.cg.shared.global [%0], [%1], 16, %2;\n"
                 :: "r"(dst), "l"(src), "r"(srcsz));
}
__device__ __forceinline__ void cpcommit() { asm volatile("cp.async.commit_group;\n"); }
template<int N> __device__ __forceinline__ void cpwait() {
    asm volatile("cp.async.wait_group %0;\n" :: "n"(N));
}

// ---------------------------------------------------------------------------
// Kernel 1: per expert e, per N-tile: gate = X@Wg, up = X@Wu, inter = silu(gate)*up
// 256 threads (8 warps, 2x4 warp grid of 32x32 warp tiles), block tile 64x128.
// 4-stage cp.async pipeline, TF32 mma, convert-on-fragment-read.
// ---------------------------------------------------------------------------
__global__ __launch_bounds__(256, 2) void moe_gateup(
    const float* __restrict__ X,
    const float* __restrict__ Wg,
    const float* __restrict__ Wu,
    const int*   __restrict__ gsz)
{
    extern __shared__ float smem[];

    const int e  = blockIdx.y;
    const int n0 = blockIdx.x * BN;

    int row_start = 0;
    for (int i = 0; i < e; i++) row_start += gsz[i];
    const int gs = gsz[e];

    const int tid  = threadIdx.x;
    const int lane = tid & 31;
    const int warp = tid >> 5;
    const int wm   = warp & 1;
    const int wn   = warp >> 1;

    const float* wg = Wg + (size_t)e * HSD * IMZD + n0;
    const float* wu = Wu + (size_t)e * HSD * IMZD + n0;

    const int am = tid >> 2;         // A row this thread loads
    const int ak = (tid & 3) * 4;    // A k-offset (float4)
    const int rm = am < gs ? am : 0; // clamped source row
    const int asz = am < gs ? 16 : 0;

    float accG[2][4][4], accU[2][4][4];
    #pragma unroll
    for (int i = 0; i < 2; i++)
        #pragma unroll
        for (int j = 0; j < 4; j++)
            #pragma unroll
            for (int k = 0; k < 4; k++) { accG[i][j][k] = 0.f; accU[i][j][k] = 0.f; }

    const int NK = HSD / KT;  // 128 stages

    auto issue = [&](int kt) {
        float* st = smem + (kt % STAGES) * STW_GU;
        const int k = kt * KT;
        // A tile (64x16): one float4 per thread, zero-fill rows >= gs
        cpa16(sptr(st + am * SA + ak),
              X + (size_t)(row_start + rm) * HSD + k + ak, asz);
        // B tiles (16x128 each): 2 float4 per thread per matrix
        #pragma unroll
        for (int i = 0; i < 2; i++) {
            int f   = tid + i * 256;
            int row = f >> 5;
            int c4  = (f & 31) * 4;
            cpa16(sptr(st + AW + row * SB + c4),
                  wg + (size_t)(k + row) * IMZD + c4, 16);
            cpa16(sptr(st + AW + BW + row * SB + c4),
                  wu + (size_t)(k + row) * IMZD + c4, 16);
        }
        cpcommit();
    };

    auto compute = [&](int b) {
        const float* st = smem + b * STW_GU;
        const float* as = st;
        const float* bg = st + AW;
        const float* bu = st + AW + BW;
        #pragma unroll
        for (int k8 = 0; k8 < 2; k8++) {
            const int kb = k8 * 8;
            unsigned a[2][4];
            #pragma unroll
            for (int mt = 0; mt < 2; mt++) {
                int r = wm * 32 + mt * 16 + (lane >> 2);
                int c = kb + (lane & 3);
                a[mt][0] = f2tf(as[r * SA + c]);
                a[mt][1] = f2tf(as[(r + 8) * SA + c]);
                a[mt][2] = f2tf(as[r * SA + c + 4]);
                a[mt][3] = f2tf(as[(r + 8) * SA + c + 4]);
            }
            #pragma unroll
            for (int nt = 0; nt < 4; nt++) {
                int col = wn * 32 + nt * 8 + (lane >> 2);
                int kr  = kb + (lane & 3);
                unsigned bG[2] = { f2tf(bg[kr * SB + col]), f2tf(bg[(kr + 4) * SB + col]) };
                unsigned bU[2] = { f2tf(bu[kr * SB + col]), f2tf(bu[(kr + 4) * SB + col]) };
                #pragma unroll
                for (int mt = 0; mt < 2; mt++) {
                    mma8(accG[mt][nt], a[mt], bG);
                    mma8(accU[mt][nt], a[mt], bU);
                }
            }
        }
    };

    // Prologue: prefetch STAGES-1 stages
    #pragma unroll
    for (int s = 0; s < STAGES - 1; s++) issue(s);

    for (int kt = 0; kt < NK; kt++) {
        cpwait<STAGES - 2>();   // stage kt complete
        __syncthreads();        // visible to all; all done computing stage kt-1
        if (kt + STAGES - 1 < NK) issue(kt + STAGES - 1);
        else cpcommit();        // keep group accounting uniform
        compute(kt % STAGES);
    }

    // Epilogue: silu(gate)*up -> g_inter
    #pragma unroll
    for (int mt = 0; mt < 2; mt++) {
        int r0 = wm * 32 + mt * 16 + (lane >> 2);
        #pragma unroll
        for (int nt = 0; nt < 4; nt++) {
            int c0 = n0 + wn * 32 + nt * 8 + 2 * (lane & 3);
            const float* cg = accG[mt][nt];
            const float* cu = accU[mt][nt];
            if (r0 < gs) {
                float g0 = cg[0], g1 = cg[1];
                float v0 = (g0 / (1.f + __expf(-g0))) * cu[0];
                float v1 = (g1 / (1.f + __expf(-g1))) * cu[1];
                *(float2*)&g_inter[(size_t)(row_start + r0) * IMZD + c0] = make_float2(v0, v1);
            }
            if (r0 + 8 < gs) {
                float g2 = cg[2], g3 = cg[3];
                float v2 = (g2 / (1.f + __expf(-g2))) * cu[2];
                float v3 = (g3 / (1.f + __expf(-g3))) * cu[3];
                *(float2*)&g_inter[(size_t)(row_start + r0 + 8) * IMZD + c0] = make_float2(v2, v3);
            }
        }
    }
}

// ---------------------------------------------------------------------------
// Kernel 2: out = inter @ Wd[e]   ([gs,1408] x [1408,2048] per expert)
// ---------------------------------------------------------------------------
__global__ __launch_bounds__(256, 2) void moe_down(
    const float* __restrict__ Wd,
    const int*   __restrict__ gsz,
    float*       __restrict__ out)
{
    extern __shared__ float smem[];

    const int e  = blockIdx.y;
    const int n0 = blockIdx.x * BN;

    int row_start = 0;
    for (int i = 0; i < e; i++) row_start += gsz[i];
    const int gs = gsz[e];

    const int tid  = threadIdx.x;
    const int lane = tid & 31;
    const int warp = tid >> 5;
    const int wm   = warp & 1;
    const int wn   = warp >> 1;

    const float* wd = Wd + (size_t)e * IMZD * HSD + n0;

    const int am = tid >> 2;
    const int ak = (tid & 3) * 4;
    const int rm = am < gs ? am : 0;
    const int asz = am < gs ? 16 : 0;

    float acc[2][4][4];
    #pragma unroll
    for (int i = 0; i < 2; i++)
        #pragma unroll
        for (int j = 0; j < 4; j++)
            #pragma unroll
            for (int k = 0; k < 4; k++) acc[i][j][k] = 0.f;

    const int NK = IMZD / KT;  // 88 stages

    auto issue = [&](int kt) {
        float* st = smem + (kt % STAGES) * STW_DN;
        const int k = kt * KT;
        cpa16(sptr(st + am * SA + ak),
              g_inter + (size_t)(row_start + rm) * IMZD + k + ak, asz);
        #pragma unroll
        for (int i = 0; i < 2; i++) {
            int f   = tid + i * 256;
            int row = f >> 5;
            int c4  = (f & 31) * 4;
            cpa16(sptr(st + AW + row * SB + c4),
                  wd + (size_t)(k + row) * HSD + c4, 16);
        }
        cpcommit();
    };

    auto compute = [&](int b) {
        const float* st = smem + b * STW_DN;
        const float* as = st;
        const float* bs = st + AW;
        #pragma unroll
        for (int k8 = 0; k8 < 2; k8++) {
            const int kb = k8 * 8;
            unsigned a[2][4];
            #pragma unroll
            for (int mt = 0; mt < 2; mt++) {
                int r = wm * 32 + mt * 16 + (lane >> 2);
                int c = kb + (lane & 3);
                a[mt][0] = f2tf(as[r * SA + c]);
                a[mt][1] = f2tf(as[(r + 8) * SA + c]);
                a[mt][2] = f2tf(as[r * SA + c + 4]);
                a[mt][3] = f2tf(as[(r + 8) * SA + c + 4]);
            }
            #pragma unroll
            for (int nt = 0; nt < 4; nt++) {
                int col = wn * 32 + nt * 8 + (lane >> 2);
                int kr  = kb + (lane & 3);
                unsigned bf[2] = { f2tf(bs[kr * SB + col]), f2tf(bs[(kr + 4) * SB + col]) };
                #pragma unroll
                for (int mt = 0; mt < 2; mt++) {
                    mma8(acc[mt][nt], a[mt], bf);
                }
            }
        }
    };

    #pragma unroll
    for (int s = 0; s < STAGES - 1; s++) issue(s);

    for (int kt = 0; kt < NK; kt++) {
        cpwait<STAGES - 2>();
        __syncthreads();
        if (kt + STAGES - 1 < NK) issue(kt + STAGES - 1);
        else cpcommit();
        compute(kt % STAGES);
    }

    // Epilogue: write output tile
    #pragma unroll
    for (int mt = 0; mt < 2; mt++) {
        int r0 = wm * 32 + mt * 16 + (lane >> 2);
        #pragma unroll
        for (int nt = 0; nt < 4; nt++) {
            int c0 = n0 + wn * 32 + nt * 8 + 2 * (lane & 3);
            const float* c = acc[mt][nt];
            if (r0 < gs)
                *(float2*)&out[(size_t)(row_start + r0) * HSD + c0] = make_float2(c[0], c[1]);
            if (r0 + 8 < gs)
                *(float2*)&out[(size_t)(row_start + r0 + 8) * HSD + c0] = make_float2(c[2], c[3]);
        }
    }
}

extern "C" void kernel_launch(void* const* d_in, const int* in_sizes, int n_in,
                              void* d_out, int out_size) {
    const float* X  = (const float*)d_in[0];  // hidden_states [T, HS]
    const float* Wg = (const float*)d_in[1];  // gate_kernel   [E, HS, IMZ]
    const float* Wu = (const float*)d_in[2];  // up_kernel     [E, HS, IMZ]
    const float* Wd = (const float*)d_in[3];  // down_kernel   [E, IMZ, HS]
    const int*   gs = (const int*)d_in[4];    // group_sizes   [E]
    float* out = (float*)d_out;               // [T, HS] fp32

    const int smem_gu = STAGES * STW_GU * 4;  // 90112 B
    const int smem_dn = STAGES * STW_DN * 4;  // 55296 B
    cudaFuncSetAttribute(moe_gateup, cudaFuncAttributeMaxDynamicSharedMemorySize, smem_gu);
    cudaFuncSetAttribute(moe_down,   cudaFuncAttributeMaxDynamicSharedMemorySize, smem_dn);

    moe_gateup<<<dim3(IMZD / BN, NEXP), 256, smem_gu>>>(X, Wg, Wu, gs);
    moe_down  <<<dim3(HSD  / BN, NEXP), 256, smem_dn>>>(Wd, gs, out);
}